// round 8
// baseline (speedup 1.0000x reference)
#include <cuda_runtime.h>

#define IMW 1024
#define IMH 1024
#define HW  (IMW * IMH)
#define SEG 16                 // output rows per thread
#define TPB 128                // threads per CTA, each owns a pixel-pair column
#define XSTR 61                // smem slot stride (ull) -> conflict-free
#define SMEM_BYTES (TPB * XSTR * 8)
#define EPSR 1e-4f
#define SGN2 0x8000000080000000ULL

typedef unsigned long long ull;

// ---- packed f32x2 helpers -------------------------------------------------
__device__ __forceinline__ ull pk2(float lo, float hi) {
    ull r;
    asm("mov.b64 %0, {%1, %2};" : "=l"(r) : "f"(lo), "f"(hi));
    return r;
}
__device__ __forceinline__ void ffma2(ull& d, ull a, ull b) {
    asm("fma.rn.f32x2 %0, %1, %2, %0;" : "+l"(d) : "l"(a), "l"(b));
}
__device__ __forceinline__ ull ffma2g(ull a, ull b, ull c) {
    ull r;
    asm("fma.rn.f32x2 %0, %1, %2, %3;" : "=l"(r) : "l"(a), "l"(b), "l"(c));
    return r;
}
__device__ __forceinline__ ull mul2(ull a, ull b) {
    ull r;
    asm("mul.rn.f32x2 %0, %1, %2;" : "=l"(r) : "l"(a), "l"(b));
    return r;
}
__device__ __forceinline__ ull add2(ull a, ull b) {
    ull r;
    asm("add.rn.f32x2 %0, %1, %2;" : "=l"(r) : "l"(a), "l"(b));
    return r;
}
__device__ __forceinline__ void upk2(ull v, float& lo, float& hi) {
    asm("mov.b64 {%0, %1}, %2;" : "=f"(lo), "=f"(hi) : "l"(v));
}
__device__ __forceinline__ float frcp(float x) {
    float r;
    asm("rcp.approx.f32 %0, %1;" : "=f"(r) : "f"(x));
    return r;
}
__host__ __device__ constexpr int IDX(int i, int j) {  // upper-tri 8x8, i<=j
    return i * 8 - i * (i - 1) / 2 + (j - i);
}

// load 11 feature channels at (row*IMW + c); EDGE: zero outside image cols
template<bool EDGE>
__device__ __forceinline__ void loadcol(float f[11],
                                        const float* __restrict__ dep,
                                        const float* __restrict__ alb,
                                        const float* __restrict__ nrm,
                                        const float* __restrict__ inp,
                                        int rb, int c) {
    if (!EDGE || (unsigned)c < (unsigned)IMW) {
        const int g = rb + c;
        f[0] = 1.0f;
        f[1] = dep[g];
        f[2] = alb[g];  f[3] = alb[g + HW];  f[4] = alb[g + 2 * HW];
        f[5] = nrm[g];  f[6] = nrm[g + HW];  f[7] = nrm[g + 2 * HW];
        f[8] = inp[g];  f[9] = inp[g + HW];  f[10] = inp[g + 2 * HW];
    } else {
#pragma unroll
        for (int ch = 0; ch < 11; ++ch) f[ch] = 0.0f;
    }
}

// accumulate (+/-) one image row's 7-tap horizontal moment sums into A[60]
template<bool EDGE, bool SUB>
__device__ __forceinline__ void addrow(ull A[60],
                                       const float* __restrict__ dep,
                                       const float* __restrict__ alb,
                                       const float* __restrict__ nrm,
                                       const float* __restrict__ inp,
                                       int r, int px) {
    const int rb = r * IMW;
    float fa[11], fb[11];
    loadcol<EDGE>(fa, dep, alb, nrm, inp, rb, px - 3);
#pragma unroll
    for (int d = 0; d < 7; ++d) {
        float* lo = (d & 1) ? fb : fa;
        float* hi = (d & 1) ? fa : fb;
        loadcol<EDGE>(hi, dep, alb, nrm, inp, rb, px - 2 + d);
        ull v[11];
#pragma unroll
        for (int ch = 0; ch < 11; ++ch) v[ch] = pk2(lo[ch], hi[ch]);
        int k = 0;
#pragma unroll
        for (int i = 0; i < 8; ++i) {
            const ull si = SUB ? (v[i] ^ SGN2) : v[i];
#pragma unroll
            for (int j = i; j < 8; ++j) { ffma2(A[k], si, v[j]); ++k; }
#pragma unroll
            for (int c = 0; c < 3; ++c) ffma2(A[36 + i * 3 + c], si, v[8 + c]);
        }
    }
}

__global__ __launch_bounds__(TPB)
void ls_kernel(const float* __restrict__ inp,
               const float* __restrict__ dep,
               const float* __restrict__ alb,
               const float* __restrict__ nrm,
               float* __restrict__ out)
{
    extern __shared__ ull X[];
    const int tid = threadIdx.x;
    const int px = blockIdx.x * (2 * TPB) + 2 * tid;   // left pixel of pair
    const int y0 = blockIdx.y * SEG;
    const bool edge = (px < 3) || (px > IMW - 5);

    ull A[60];
#pragma unroll
    for (int m = 0; m < 60; ++m) A[m] = 0ULL;

    // ---- prologue: A = sum of h(r), r = y0-3 .. y0+3 (clipped) ----
#pragma unroll 1
    for (int r = y0 - 3; r <= y0 + 3; ++r) {
        if ((unsigned)r < (unsigned)IMH) {
            if (!edge) addrow<false, false>(A, dep, alb, nrm, inp, r, px);
            else       addrow<true,  false>(A, dep, alb, nrm, inp, r, px);
        }
    }

    ull* xp = X + tid * XSTR;
    const ull EPS2 = pk2(EPSR, EPSR);

#pragma unroll 1
    for (int k = 0; k < SEG; ++k) {
        const int y = y0 + k;
        if (k > 0) {
            const int rn = y + 3, ro = y - 4;
            if ((unsigned)rn < (unsigned)IMH) {
                if (!edge) addrow<false, false>(A, dep, alb, nrm, inp, rn, px);
                else       addrow<true,  false>(A, dep, alb, nrm, inp, rn, px);
            }
            if ((unsigned)ro < (unsigned)IMH) {
                if (!edge) addrow<false, true>(A, dep, alb, nrm, inp, ro, px);
                else       addrow<true,  true>(A, dep, alb, nrm, inp, ro, px);
            }
        }

        // ---- stash A in private smem slot (A regs die here) ----
#pragma unroll
        for (int m = 0; m < 60; ++m) xp[m] = A[m];

        // ---- packed symmetric solve on a copy ----
        ull w[36];
#pragma unroll
        for (int m = 0; m < 36; ++m) w[m] = xp[m];
#pragma unroll
        for (int i = 0; i < 8; ++i) w[IDX(i, i)] = add2(w[IDX(i, i)], EPS2);

        ull rhs[8];
        {
            const int g = y * IMW + px;
            rhs[0] = pk2(1.0f, 1.0f);
            float2 t;
            t = *(const float2*)(dep + g);          rhs[1] = pk2(t.x, t.y);
            t = *(const float2*)(alb + g);          rhs[2] = pk2(t.x, t.y);
            t = *(const float2*)(alb + g + HW);     rhs[3] = pk2(t.x, t.y);
            t = *(const float2*)(alb + g + 2 * HW); rhs[4] = pk2(t.x, t.y);
            t = *(const float2*)(nrm + g);          rhs[5] = pk2(t.x, t.y);
            t = *(const float2*)(nrm + g + HW);     rhs[6] = pk2(t.x, t.y);
            t = *(const float2*)(nrm + g + 2 * HW); rhs[7] = pk2(t.x, t.y);
        }

#pragma unroll
        for (int kk = 0; kk < 8; ++kk) {
            float dlo, dhi;
            upk2(w[IDX(kk, kk)], dlo, dhi);
            const ull ninv = pk2(-frcp(dlo), -frcp(dhi));
#pragma unroll
            for (int i = kk + 1; i < 8; ++i) {
                const ull li = mul2(w[IDX(kk, i)], ninv);   // -a_ki / d_k
                rhs[i] = ffma2g(li, rhs[kk], rhs[i]);
#pragma unroll
                for (int j = i; j < 8; ++j)
                    w[IDX(i, j)] = ffma2g(li, w[IDX(kk, j)], w[IDX(i, j)]);
            }
        }
        ull nx[8];
#pragma unroll
        for (int i = 7; i >= 0; --i) {
            ull s = rhs[i];
#pragma unroll
            for (int j = 7; j > i; --j)
                s = ffma2g(w[IDX(i, j)], nx[j], s);
            float dlo, dhi;
            upk2(w[IDX(i, i)], dlo, dhi);
            nx[i] = mul2(s, pk2(-frcp(dlo), -frcp(dhi)));
        }

        // out_c = x . AtY_c = -(nx . AtY_c); AtY read back from smem slot
#pragma unroll
        for (int c = 0; c < 3; ++c) {
            ull a2 = 0ULL;
#pragma unroll
            for (int i = 0; i < 8; ++i)
                ffma2(a2, nx[i], xp[36 + i * 3 + c]);
            float olo, ohi;
            upk2(a2, olo, ohi);
            *(float2*)(out + c * HW + y * IMW + px) = make_float2(-olo, -ohi);
        }

        // ---- reload A for the next slide ----
#pragma unroll
        for (int m = 0; m < 60; ++m) A[m] = xp[m];
    }
}

extern "C" void kernel_launch(void* const* d_in, const int* in_sizes, int n_in,
                              void* d_out, int out_size) {
    const float* inp   = (const float*)d_in[0];
    const float* depth = (const float*)d_in[1];
    const float* alb   = (const float*)d_in[2];
    const float* nrm   = (const float*)d_in[3];
    float* out = (float*)d_out;

    cudaFuncSetAttribute(ls_kernel, cudaFuncAttributeMaxDynamicSharedMemorySize,
                         SMEM_BYTES);
    dim3 grid(IMW / (2 * TPB), IMH / SEG);   // (4, 64)
    ls_kernel<<<grid, TPB, SMEM_BYTES>>>(inp, depth, alb, nrm, out);
}

// round 9
// speedup vs baseline: 1.2557x; 1.2557x over previous
#include <cuda_runtime.h>

#define IMW 1024
#define IMH 1024
#define HW  (IMW * IMH)
#define TW 16
#define TH 64
#define HALO_W 22
#define HALO_H 70
#define SSTRIDE 24
#define CH_STRIDE (HALO_H * SSTRIDE)    // 1680 floats per channel
#define F_WORDS (11 * CH_STRIDE)        // 18480
#define XSLOTS 64
#define XSTR 61
#define X_ULL (XSLOTS * XSTR)
#define SMEM_BYTES (F_WORDS * 4 + X_ULL * 8)   // 73920 + 31232 = 105152
#define EPSR 1e-4f
#define SGN2 0x8000000080000000ULL

typedef unsigned long long ull;

// ---- packed f32x2 helpers -------------------------------------------------
__device__ __forceinline__ ull pk2(float lo, float hi) {
    ull r;
    asm("mov.b64 %0, {%1, %2};" : "=l"(r) : "f"(lo), "f"(hi));
    return r;
}
__device__ __forceinline__ void ffma2(ull& d, ull a, ull b) {
    asm("fma.rn.f32x2 %0, %1, %2, %0;" : "+l"(d) : "l"(a), "l"(b));
}
__device__ __forceinline__ ull ffma2g(ull a, ull b, ull c) {
    ull r;
    asm("fma.rn.f32x2 %0, %1, %2, %3;" : "=l"(r) : "l"(a), "l"(b), "l"(c));
    return r;
}
__device__ __forceinline__ ull mul2(ull a, ull b) {
    ull r;
    asm("mul.rn.f32x2 %0, %1, %2;" : "=l"(r) : "l"(a), "l"(b));
    return r;
}
__device__ __forceinline__ ull add2(ull a, ull b) {
    ull r;
    asm("add.rn.f32x2 %0, %1, %2;" : "=l"(r) : "l"(a), "l"(b));
    return r;
}
__device__ __forceinline__ void upk2(ull v, float& lo, float& hi) {
    asm("mov.b64 {%0, %1}, %2;" : "=f"(lo), "=f"(hi) : "l"(v));
}
__device__ __forceinline__ float frcp(float x) {
    float r;
    asm("rcp.approx.f32 %0, %1;" : "=f"(r) : "f"(x));
    return r;
}
__host__ __device__ constexpr int IDX(int i, int j) {  // upper-tri 8x8, i<=j
    return i * 8 - i * (i - 1) / 2 + (j - i);
}

// 7 horizontal taps at one row-pair base; SUB subtracts instead of adding.
// rp points at &S[base_row*SSTRIDE + lx]; pixel_a uses row base, pixel_b base+1.
template<bool SUB>
__device__ __forceinline__ void tap7(const float* __restrict__ rp, ull A[60]) {
#pragma unroll
    for (int dx = 0; dx < 7; ++dx) {
        ull v[11];
#pragma unroll
        for (int ch = 0; ch < 11; ++ch)
            v[ch] = pk2(rp[ch * CH_STRIDE + dx],
                        rp[ch * CH_STRIDE + dx + SSTRIDE]);
        int k = 0;
#pragma unroll
        for (int i = 0; i < 8; ++i) {
            const ull si = SUB ? (v[i] ^ SGN2) : v[i];
#pragma unroll
            for (int j = i; j < 8; ++j) { ffma2(A[k], si, v[j]); ++k; }
#pragma unroll
            for (int c = 0; c < 3; ++c) ffma2(A[36 + i * 3 + c], si, v[8 + c]);
        }
    }
}

// packed solve + output; A is stashed at xp (A[0..35]=AtA tri, A[36..59]=AtY)
__device__ __forceinline__ void solve_out(const ull* __restrict__ xp,
                                          const float* __restrict__ S,
                                          int lp, int lx, int gy, int gx,
                                          float* __restrict__ out) {
    ull w[36];
#pragma unroll
    for (int m = 0; m < 36; ++m) w[m] = xp[m];
    const ull EPS2 = pk2(EPSR, EPSR);
#pragma unroll
    for (int i = 0; i < 8; ++i) w[IDX(i, i)] = add2(w[IDX(i, i)], EPS2);

    ull rhs[8];
    {
        const float* cp = &S[(lp + 3) * SSTRIDE + (lx + 3)];
#pragma unroll
        for (int ch = 0; ch < 8; ++ch)
            rhs[ch] = pk2(cp[ch * CH_STRIDE], cp[ch * CH_STRIDE + SSTRIDE]);
    }

#pragma unroll
    for (int k = 0; k < 8; ++k) {
        float dlo, dhi;
        upk2(w[IDX(k, k)], dlo, dhi);
        const ull ninv = pk2(-frcp(dlo), -frcp(dhi));
#pragma unroll
        for (int i = k + 1; i < 8; ++i) {
            const ull li = mul2(w[IDX(k, i)], ninv);   // -a_ki / d_k
            rhs[i] = ffma2g(li, rhs[k], rhs[i]);
#pragma unroll
            for (int j = i; j < 8; ++j)
                w[IDX(i, j)] = ffma2g(li, w[IDX(k, j)], w[IDX(i, j)]);
        }
    }
    ull nx[8];
#pragma unroll
    for (int i = 7; i >= 0; --i) {
        ull s = rhs[i];
#pragma unroll
        for (int j = 7; j > i; --j)
            s = ffma2g(w[IDX(i, j)], nx[j], s);
        float dlo, dhi;
        upk2(w[IDX(i, i)], dlo, dhi);
        nx[i] = mul2(s, pk2(-frcp(dlo), -frcp(dhi)));
    }

#pragma unroll
    for (int c = 0; c < 3; ++c) {
        ull a2 = 0ULL;
#pragma unroll
        for (int i = 0; i < 8; ++i)
            ffma2(a2, nx[i], xp[36 + i * 3 + c]);
        float olo, ohi;
        upk2(a2, olo, ohi);
        out[c * HW + gy * IMW + gx]       = -olo;
        out[c * HW + (gy + 1) * IMW + gx] = -ohi;
    }
}

__global__ __launch_bounds__(128)
void ls_kernel(const float* __restrict__ inp,
               const float* __restrict__ dep,
               const float* __restrict__ alb,
               const float* __restrict__ nrm,
               float* __restrict__ out)
{
    extern __shared__ float SM[];
    float* S = SM;                          // S[ch][r][c], stride 24
    ull* X = (ull*)(SM + F_WORDS);          // stash: 64 slots x 61 ull

    const int tid = threadIdx.x;
    const int bx = blockIdx.x, by = blockIdx.y;
    const int gx0 = bx * TW - 3;
    const int gy0 = by * TH - 3;

    // ---- stage halo features (zeros outside image) ----
    for (int idx = tid; idx < HALO_H * HALO_W; idx += 128) {
        const int r = idx / HALO_W;
        const int c = idx - r * HALO_W;
        const int gy = gy0 + r;
        const int gx = gx0 + c;
        float v[11];
        if ((unsigned)gy < (unsigned)IMH && (unsigned)gx < (unsigned)IMW) {
            const int g = gy * IMW + gx;
            v[0] = 1.0f;
            v[1] = dep[g];
            v[2] = alb[g];  v[3] = alb[g + HW];  v[4] = alb[g + 2 * HW];
            v[5] = nrm[g];  v[6] = nrm[g + HW];  v[7] = nrm[g + 2 * HW];
            v[8] = inp[g];  v[9] = inp[g + HW];  v[10] = inp[g + 2 * HW];
        } else {
#pragma unroll
            for (int ch = 0; ch < 11; ++ch) v[ch] = 0.0f;
        }
#pragma unroll
        for (int ch = 0; ch < 11; ++ch)
            S[ch * CH_STRIDE + r * SSTRIDE + c] = v[ch];
    }
    __syncthreads();

    const int lx = tid & 15;
    const int ty = tid >> 4;                // 0..7
    const int lp0 = 8 * ty;                 // first output row of this thread
    const int half = tid >> 6;              // warps 0-1 vs 2-3 (no divergence)
    ull* xp = X + (tid & 63) * XSTR;

    ull A[60];
#pragma unroll
    for (int m = 0; m < 60; ++m) A[m] = 0ULL;

    // ---- prologue: pair 0 = full 49 taps ----
    {
        const float* b = &S[lp0 * SSTRIDE + lx];
#pragma unroll
        for (int dy = 0; dy < 7; ++dy)
            tap7<false>(b + dy * SSTRIDE, A);
    }

#pragma unroll 1
    for (int k = 0; k < 4; ++k) {
        const int lp = lp0 + 2 * k;
        if (k > 0) {
            // slide by 2 rows: +bases lp+5, lp+6 ; -bases lp-2, lp-1
            const float* b = &S[lp * SSTRIDE + lx];
            tap7<false>(b + 5 * SSTRIDE, A);
            tap7<false>(b + 6 * SSTRIDE, A);
            tap7<true >(b - 2 * SSTRIDE, A);
            tap7<true >(b - 1 * SSTRIDE, A);
        }

        const int gy = by * TH + lp;
        const int gx = bx * TW + lx;

        if (half == 0) {
#pragma unroll
            for (int m = 0; m < 60; ++m) xp[m] = A[m];   // stash (A regs die)
            solve_out(xp, S, lp, lx, gy, gx, out);
            if (k < 3) {
#pragma unroll
                for (int m = 0; m < 60; ++m) A[m] = xp[m];  // restore
            }
        }
        __syncthreads();
        if (half == 1) {
#pragma unroll
            for (int m = 0; m < 60; ++m) xp[m] = A[m];
            solve_out(xp, S, lp, lx, gy, gx, out);
            if (k < 3) {
#pragma unroll
                for (int m = 0; m < 60; ++m) A[m] = xp[m];
            }
        }
        __syncthreads();
    }
}

extern "C" void kernel_launch(void* const* d_in, const int* in_sizes, int n_in,
                              void* d_out, int out_size) {
    const float* inp   = (const float*)d_in[0];
    const float* depth = (const float*)d_in[1];
    const float* alb   = (const float*)d_in[2];
    const float* nrm   = (const float*)d_in[3];
    float* out = (float*)d_out;

    cudaFuncSetAttribute(ls_kernel, cudaFuncAttributeMaxDynamicSharedMemorySize,
                         SMEM_BYTES);
    dim3 grid(IMW / TW, IMH / TH);   // (64, 16) = 1024 CTAs
    ls_kernel<<<grid, 128, SMEM_BYTES>>>(inp, depth, alb, nrm, out);
}